// round 6
// baseline (speedup 1.0000x reference)
#include <cuda_runtime.h>

#define N 8192
#define F 128
#define ALPHA 0.2f
#define NCTA 888   // 148 SMs x 6 guaranteed-resident CTAs (launch_bounds(256,6))

// Allocation-free scratch
__device__ float g_Wa1[F];
__device__ float g_Wa2[F];
__device__ float g_si[N];
__device__ float g_sj[N];
__device__ int   g_ctrA;
__device__ int   g_ctrB;
__device__ int   g_done;

__global__ __launch_bounds__(256, 6) void gat_fused_kernel(
    const float* __restrict__ vi, const float* __restrict__ vj,
    const float* __restrict__ W,  const float* __restrict__ a,
    const int* __restrict__ adj,  float* __restrict__ out) {
    __shared__ float sred[2 * F];   // phase A reduction
    __shared__ float red[8];
    __shared__ float bcast;

    const int tid  = threadIdx.x;
    const int lane = tid & 31;
    const int wid  = tid >> 5;
    const int b    = blockIdx.x;

    // ---------------- Phase A: CTA b (<128) computes Wa1[b], Wa2[b] ----------
    if (b < F) {
        if (tid < F) {
            float w = W[b * F + tid];
            sred[tid]     = w * a[tid];
            sred[F + tid] = w * a[F + tid];
        }
        __syncthreads();
        if (wid == 0) {
            float s1 = sred[lane] + sred[lane + 32] + sred[lane + 64] + sred[lane + 96];
            float s2 = sred[F + lane] + sred[F + lane + 32] + sred[F + lane + 64] + sred[F + lane + 96];
#pragma unroll
            for (int o = 16; o > 0; o >>= 1) {
                s1 += __shfl_down_sync(0xffffffffu, s1, o);
                s2 += __shfl_down_sync(0xffffffffu, s2, o);
            }
            if (lane == 0) {
                g_Wa1[b] = s1;
                g_Wa2[b] = s2;
                __threadfence();                 // publish (writer == fencer)
                atomicAdd(&g_ctrA, 1);
            }
        }
    }
    // acquire Wa
    if (tid == 0) {
        while (atomicAdd(&g_ctrA, 0) < F) __nanosleep(64);
        __threadfence();                         // invalidate L1 before reading g_Wa
    }
    __syncthreads();

    // ---------------- Phase B: warp-per-row si/sj ----------------------------
    {
        float4 a1 = reinterpret_cast<const float4*>(g_Wa1)[lane];
        float4 a2 = reinterpret_cast<const float4*>(g_Wa2)[lane];
        for (int base = b * 8; base < N; base += NCTA * 8) {
            const int row = base + wid;
            float4 x1 = reinterpret_cast<const float4*>(vi + (size_t)row * F)[lane];
            float4 x2 = reinterpret_cast<const float4*>(vj + (size_t)row * F)[lane];
            float s1 = fmaf(x1.x, a1.x, fmaf(x1.y, a1.y, fmaf(x1.z, a1.z, x1.w * a1.w)));
            float s2 = fmaf(x2.x, a2.x, fmaf(x2.y, a2.y, fmaf(x2.z, a2.z, x2.w * a2.w)));
#pragma unroll
            for (int o = 16; o > 0; o >>= 1) {
                s1 += __shfl_down_sync(0xffffffffu, s1, o);
                s2 += __shfl_down_sync(0xffffffffu, s2, o);
            }
            if (lane == 0) {
                g_si[row] = s1;
                g_sj[row] = s2;
            }
        }
    }
    __syncthreads();                             // all warps' si/sj stores done
    if (tid == 0) {
        __threadfence();                         // publish this CTA's stores
        atomicAdd(&g_ctrB, 1);
        while (atomicAdd(&g_ctrB, 0) < NCTA) __nanosleep(64);
        __threadfence();                         // invalidate L1 before reading g_si/g_sj
    }
    __syncthreads();

    // ---------------- Phase C: persistent softmax ----------------------------
    const float4* sj4 = reinterpret_cast<const float4*>(g_sj);
    for (int row = b; row < N; row += NCTA) {
        const float si = g_si[row];
        const int4* adj4 = reinterpret_cast<const int4*>(adj + (size_t)row * N);
        float4* out4 = reinterpret_cast<float4*>(out + (size_t)row * N);

        float4 preg[8];
        float lsum = 0.f;
#pragma unroll
        for (int it = 0; it < 8; ++it) {
            const int j = tid + it * 256;
            int4   av = __ldcs(&adj4[j]);
            float4 sj = sj4[j];
            float4 p;
            float t;
            t = si + sj.x; t = t > 0.f ? t : ALPHA * t; p.x = av.x > 0 ? __expf(t) : 0.f;
            t = si + sj.y; t = t > 0.f ? t : ALPHA * t; p.y = av.y > 0 ? __expf(t) : 0.f;
            t = si + sj.z; t = t > 0.f ? t : ALPHA * t; p.z = av.z > 0 ? __expf(t) : 0.f;
            t = si + sj.w; t = t > 0.f ? t : ALPHA * t; p.w = av.w > 0 ? __expf(t) : 0.f;
            preg[it] = p;
            lsum += (p.x + p.y) + (p.z + p.w);
        }
#pragma unroll
        for (int o = 16; o > 0; o >>= 1)
            lsum += __shfl_xor_sync(0xffffffffu, lsum, o);
        if (lane == 0) red[wid] = lsum;
        __syncthreads();
        if (wid == 0) {
            float s = (lane < 8) ? red[lane] : 0.f;
#pragma unroll
            for (int o = 4; o > 0; o >>= 1)
                s += __shfl_xor_sync(0xffffffffu, s, o);
            if (lane == 0) bcast = 1.0f / s;
        }
        __syncthreads();
        const float inv = bcast;

#pragma unroll
        for (int it = 0; it < 8; ++it) {
            float4 p = preg[it];
            p.x *= inv; p.y *= inv; p.z *= inv; p.w *= inv;
            __stcs(&out4[tid + it * 256], p);
        }
    }

    // ---------------- Epilogue: last CTA resets counters for graph replay ----
    __syncthreads();
    if (tid == 0) {
        int v = atomicAdd(&g_done, 1);
        if (v == NCTA - 1) {
            g_ctrA = 0;
            g_ctrB = 0;
            g_done = 0;
        }
    }
}

extern "C" void kernel_launch(void* const* d_in, const int* in_sizes, int n_in,
                              void* d_out, int out_size) {
    const float* v_i = (const float*)d_in[0];
    const float* v_j = (const float*)d_in[1];
    const int*   adj = (const int*)d_in[2];
    const float* W   = (const float*)d_in[3];
    const float* a   = (const float*)d_in[4];
    float* out = (float*)d_out;

    gat_fused_kernel<<<NCTA, 256>>>(v_i, v_j, W, a, adj, out);
}

// round 7
// speedup vs baseline: 1.1326x; 1.1326x over previous
#include <cuda_runtime.h>

#define N 8192
#define F 128
#define ALPHA 0.2f

// Allocation-free scratch
__device__ float g_si[N];
__device__ float g_sj[N];

// Prologue: grid 256 x 1024 threads, single wave.
// Triggers PDL completion at entry so the softmax kernel can start launching
// and prefetching adj while this runs.
__global__ __launch_bounds__(1024) void prologue_kernel(
    const float* __restrict__ vi, const float* __restrict__ vj,
    const float* __restrict__ W, const float* __restrict__ a) {
#if __CUDA_ARCH__ >= 900
    cudaTriggerProgrammaticLaunchCompletion();
#endif
    __shared__ float sa1[F];
    __shared__ float sa2[F];
    __shared__ float sWa1[F];
    __shared__ float sWa2[F];

    const int tid = threadIdx.x;
    const int lane = tid & 31;
    const int wid = tid >> 5;

    if (tid < F)            sa1[tid] = a[tid];
    else if (tid < 2 * F)   sa2[tid - F] = a[tid];
    __syncthreads();

    // Phase 1: warp w computes Wa rows w*4 .. w*4+3 (coalesced float4)
    {
        const float4 a1v = reinterpret_cast<const float4*>(sa1)[lane];
        const float4 a2v = reinterpret_cast<const float4*>(sa2)[lane];
#pragma unroll
        for (int r = 0; r < 4; ++r) {
            const int row = wid * 4 + r;
            float4 wv = reinterpret_cast<const float4*>(W + row * F)[lane];
            float s1 = fmaf(wv.x, a1v.x, fmaf(wv.y, a1v.y, fmaf(wv.z, a1v.z, wv.w * a1v.w)));
            float s2 = fmaf(wv.x, a2v.x, fmaf(wv.y, a2v.y, fmaf(wv.z, a2v.z, wv.w * a2v.w)));
#pragma unroll
            for (int o = 16; o > 0; o >>= 1) {
                s1 += __shfl_xor_sync(0xffffffffu, s1, o);
                s2 += __shfl_xor_sync(0xffffffffu, s2, o);
            }
            if (lane == 0) { sWa1[row] = s1; sWa2[row] = s2; }
        }
    }
    __syncthreads();

    // Phase 2: one warp per row (32 warps/block, 256 blocks = 8192 rows)
    const int row = blockIdx.x * 32 + wid;
    float4 a1 = reinterpret_cast<const float4*>(sWa1)[lane];
    float4 a2 = reinterpret_cast<const float4*>(sWa2)[lane];
    float4 x1 = reinterpret_cast<const float4*>(vi + (size_t)row * F)[lane];
    float4 x2 = reinterpret_cast<const float4*>(vj + (size_t)row * F)[lane];

    float s1 = fmaf(x1.x, a1.x, fmaf(x1.y, a1.y, fmaf(x1.z, a1.z, x1.w * a1.w)));
    float s2 = fmaf(x2.x, a2.x, fmaf(x2.y, a2.y, fmaf(x2.z, a2.z, x2.w * a2.w)));

#pragma unroll
    for (int o = 16; o > 0; o >>= 1) {
        s1 += __shfl_down_sync(0xffffffffu, s1, o);
        s2 += __shfl_down_sync(0xffffffffu, s2, o);
    }
    if (lane == 0) {
        g_si[row] = s1;
        g_sj[row] = s2;
    }
}

// Softmax (R3 body, unchanged math): one block per row, register-staged p.
// PDL: prefetch this row's adj into L2 BEFORE the grid-dependency sync so the
// DRAM fetch overlaps the prologue kernel; then sync and run as before.
__global__ __launch_bounds__(256, 8) void softmax_row_kernel(
    const int* __restrict__ adj, float* __restrict__ out) {
    __shared__ float red[8];
    __shared__ float bcast;

    const int row = blockIdx.x;
    const int tid = threadIdx.x;
    const int lane = tid & 31;
    const int wid = tid >> 5;

    const int4*   adj4 = reinterpret_cast<const int4*>(adj + (size_t)row * N);
    const float4* sj4  = reinterpret_cast<const float4*>(g_sj);
    float4* out4 = reinterpret_cast<float4*>(out + (size_t)row * N);

    // Prologue-independent: pull adj row toward L2 (no registers held).
#pragma unroll
    for (int it = 0; it < 8; ++it) {
        asm volatile("prefetch.global.L2 [%0];" :: "l"(adj4 + tid + it * 256));
    }
#if __CUDA_ARCH__ >= 900
    cudaGridDependencySynchronize();
#endif

    const float si = g_si[row];
    float4 preg[8];
    float lsum = 0.f;
#pragma unroll
    for (int it = 0; it < 8; ++it) {
        const int j = tid + it * 256;
        int4   av = __ldcs(&adj4[j]);
        float4 sj = sj4[j];
        float4 p;
        float t;
        t = si + sj.x; t = t > 0.f ? t : ALPHA * t; p.x = av.x > 0 ? __expf(t) : 0.f;
        t = si + sj.y; t = t > 0.f ? t : ALPHA * t; p.y = av.y > 0 ? __expf(t) : 0.f;
        t = si + sj.z; t = t > 0.f ? t : ALPHA * t; p.z = av.z > 0 ? __expf(t) : 0.f;
        t = si + sj.w; t = t > 0.f ? t : ALPHA * t; p.w = av.w > 0 ? __expf(t) : 0.f;
        preg[it] = p;
        lsum += (p.x + p.y) + (p.z + p.w);
    }
#pragma unroll
    for (int o = 16; o > 0; o >>= 1)
        lsum += __shfl_xor_sync(0xffffffffu, lsum, o);
    if (lane == 0) red[wid] = lsum;
    __syncthreads();
    if (wid == 0) {
        float s = (lane < 8) ? red[lane] : 0.f;
#pragma unroll
        for (int o = 4; o > 0; o >>= 1)
            s += __shfl_xor_sync(0xffffffffu, s, o);
        if (lane == 0) bcast = 1.0f / s;
    }
    __syncthreads();
    const float inv = bcast;

#pragma unroll
    for (int it = 0; it < 8; ++it) {
        float4 p = preg[it];
        p.x *= inv; p.y *= inv; p.z *= inv; p.w *= inv;
        __stcs(&out4[tid + it * 256], p);
    }
}

extern "C" void kernel_launch(void* const* d_in, const int* in_sizes, int n_in,
                              void* d_out, int out_size) {
    const float* v_i = (const float*)d_in[0];
    const float* v_j = (const float*)d_in[1];
    const int*   adj = (const int*)d_in[2];
    const float* W   = (const float*)d_in[3];
    const float* a   = (const float*)d_in[4];
    float* out = (float*)d_out;

    prologue_kernel<<<256, 1024>>>(v_i, v_j, W, a);

    // Softmax with programmatic dependent launch (overlaps with prologue).
    cudaLaunchConfig_t cfg = {};
    cfg.gridDim = dim3(N, 1, 1);
    cfg.blockDim = dim3(256, 1, 1);
    cfg.dynamicSmemBytes = 0;
    cfg.stream = 0;  // same (legacy default) stream the harness captures
    cudaLaunchAttribute attrs[1];
    attrs[0].id = cudaLaunchAttributeProgrammaticStreamSerialization;
    attrs[0].val.programmaticStreamSerializationAllowed = 1;
    cfg.attrs = attrs;
    cfg.numAttrs = 1;
    cudaLaunchKernelEx(&cfg, softmax_row_kernel, adj, out);
}